// round 5
// baseline (speedup 1.0000x reference)
#include <cuda_runtime.h>
#include <math.h>

typedef unsigned long long ull;

#define BB   8192
#define VV   100000
#define ND   15
#define SL   50
#define HID  30

// X scratch in f32x2 slot layout: [row][slot i=0..17][lane 0..31]
//   i<16 : dims {64*i + 2l, 64*i + 2l + 1}  (feature i)
//   i=16 : pairwise lp values {p=l, p=l+32}
//   i=17 : pairwise lp values {p=l+64, p=l+96}  (y=0 for l>=24)
__device__ ull g_X[(size_t)BB * 18 * 32];
// W1 permuted to match the slot layout: [j][slot][lane], f32x2 packed
__device__ ull g_W1L[HID * 18 * 32];

// ---------------- f32x2 helpers (Blackwell packed fp32) ----------------
__device__ __forceinline__ ull f2_pack(float x, float y) {
    ull r; asm("mov.b64 %0, {%1, %2};" : "=l"(r) : "f"(x), "f"(y)); return r;
}
__device__ __forceinline__ ull f2_mul(ull a, ull b) {
    ull r; asm("mul.rn.f32x2 %0, %1, %2;" : "=l"(r) : "l"(a), "l"(b)); return r;
}
__device__ __forceinline__ ull f2_add(ull a, ull b) {
    ull r; asm("add.rn.f32x2 %0, %1, %2;" : "=l"(r) : "l"(a), "l"(b)); return r;
}
__device__ __forceinline__ void f2_fma(ull& d, ull a, ull b) {
    asm("fma.rn.f32x2 %0, %1, %2, %0;" : "+l"(d) : "l"(a), "l"(b));
}
__device__ __forceinline__ float f2_hadd(ull a) {
    float lo, hi; asm("mov.b64 {%0, %1}, %2;" : "=f"(lo), "=f"(hi) : "l"(a));
    return lo + hi;
}

// ---------------- prep: permute W1 into slot layout ----------------
__global__ void prep_kernel(const float* __restrict__ W1) {
    int idx = blockIdx.x * blockDim.x + threadIdx.x;
    if (idx >= HID * 18 * 32) return;
    int j = idx / 576;
    int rem = idx - j * 576;
    int i = rem >> 5;
    int l = rem & 31;
    int k0, k1;
    if (i < 16)       { k0 = i * 64 + 2 * l;  k1 = k0 + 1; }
    else if (i == 16) { k0 = 1024 + l;        k1 = 1024 + 32 + l; }
    else              { k0 = 1024 + 64 + l;   k1 = 1024 + 96 + l; }
    float x = W1[k0 * HID + j];
    float y = (k1 < 1144) ? W1[k1 * HID + j] : 0.0f;
    g_W1L[idx] = f2_pack(x, y);
}

// ---------------- K1: warp-per-row gather + register pairwise ----------------
__global__ __launch_bounds__(256) void gather_kernel(
    const int*   __restrict__ dense_ids,
    const int*   __restrict__ seq_ids,
    const float* __restrict__ tables_dense,
    const float* __restrict__ table_seq,
    const float* __restrict__ inner_w)
{
    const int l = threadIdx.x & 31;
    const int w = threadIdx.x >> 5;
    const int row = blockIdx.x * 8 + w;

    // gather dense features (random DRAM, 15 independent loads in flight)
    ull e[16];
    const ull* td = (const ull*)tables_dense;  // f32x2 view, 32 per embedding row
    const int* dr = dense_ids + row * ND;
    #pragma unroll
    for (int f = 0; f < ND; f++) {
        int id = __ldg(dr + f);
        e[f] = __ldg(td + ((size_t)f * VV + (size_t)id) * 32 + l);
    }

    // sequence mean (feature 15) — L2-resident table
    const int* sr = seq_ids + row * SL;
    const ull* ts = (const ull*)table_seq;
    ull acc = 0;  // bit pattern 0 == (0.f, 0.f)
    #pragma unroll 10
    for (int s = 0; s < SL; s++) {
        int id = __ldg(sr + s);
        acc = f2_add(acc, __ldg(ts + (size_t)id * 32 + l));
    }
    e[15] = f2_mul(acc, f2_pack(1.0f / 50.0f, 1.0f / 50.0f));

    // write feature slots (coalesced)
    ull* Xr = g_X + (size_t)row * 576;
    #pragma unroll
    for (int f = 0; f < 16; f++) Xr[f * 32 + l] = e[f];

    // pairwise inner products, fully static pair enumeration
    const ull* iw = (const ull*)inner_w;
    float lp0 = 0.f, lp1 = 0.f, lp2 = 0.f, lp3 = 0.f;
    int p = 0;
    #pragma unroll
    for (int a = 0; a < 15; a++) {
        #pragma unroll
        for (int b = a + 1; b < 16; b++) {
            ull w2 = __ldg(iw + p * 32 + l);
            ull t  = f2_mul(f2_mul(e[a], e[b]), w2);
            float s = f2_hadd(t);
            s += __shfl_xor_sync(0xffffffffu, s, 16);
            s += __shfl_xor_sync(0xffffffffu, s, 8);
            s += __shfl_xor_sync(0xffffffffu, s, 4);
            s += __shfl_xor_sync(0xffffffffu, s, 2);
            s += __shfl_xor_sync(0xffffffffu, s, 1);
            // lane (p & 31) keeps pair p in its slot group (p >> 5)
            if ((p & 31) == l) {
                switch (p >> 5) {
                    case 0: lp0 = s; break;
                    case 1: lp1 = s; break;
                    case 2: lp2 = s; break;
                    default: lp3 = s; break;
                }
            }
            p++;
        }
    }
    Xr[16 * 32 + l] = f2_pack(lp0, lp1);
    Xr[17 * 32 + l] = f2_pack(lp2, lp3);
}

// ---------------- K2: MLP GEMV, 4 rows per warp, FFMA2 ----------------
__global__ __launch_bounds__(256) void mlp_kernel(
    const float* __restrict__ b1,
    const float* __restrict__ W2,
    const float* __restrict__ b2,
    float*       __restrict__ out)
{
    const int l = threadIdx.x & 31;
    const int w = threadIdx.x >> 5;
    const int g = blockIdx.x * 8 + w;           // rows 4g .. 4g+3

    const ull* X0 = g_X + (size_t)(4 * g) * 576;
    ull x0[18], x1[18], x2[18], x3[18];
    #pragma unroll
    for (int i = 0; i < 18; i++) {
        x0[i] = X0[          i * 32 + l];
        x1[i] = X0[ 576 +    i * 32 + l];
        x2[i] = X0[1152 +    i * 32 + l];
        x3[i] = X0[1728 +    i * 32 + l];
    }

    float z0 = 0.f, z1 = 0.f, z2 = 0.f, z3 = 0.f;
    for (int j = 0; j < HID; j++) {
        ull a0 = 0, a1 = 0, a2 = 0, a3 = 0;
        const ull* wj = g_W1L + j * 576 + l;
        #pragma unroll
        for (int i = 0; i < 18; i++) {
            ull ww = __ldg(wj + i * 32);        // coalesced, L1-resident
            f2_fma(a0, x0[i], ww);
            f2_fma(a1, x1[i], ww);
            f2_fma(a2, x2[i], ww);
            f2_fma(a3, x3[i], ww);
        }
        float s0 = f2_hadd(a0), s1 = f2_hadd(a1);
        float s2 = f2_hadd(a2), s3 = f2_hadd(a3);
        #pragma unroll
        for (int o = 16; o; o >>= 1) {
            s0 += __shfl_xor_sync(0xffffffffu, s0, o);
            s1 += __shfl_xor_sync(0xffffffffu, s1, o);
            s2 += __shfl_xor_sync(0xffffffffu, s2, o);
            s3 += __shfl_xor_sync(0xffffffffu, s3, o);
        }
        float bj  = __ldg(b1 + j);
        float w2j = __ldg(W2 + j);
        z0 += fmaxf(s0 + bj, 0.f) * w2j;
        z1 += fmaxf(s1 + bj, 0.f) * w2j;
        z2 += fmaxf(s2 + bj, 0.f) * w2j;
        z3 += fmaxf(s3 + bj, 0.f) * w2j;
    }
    if (l == 0) {
        float bo = __ldg(b2);
        out[4 * g + 0] = 1.0f / (1.0f + expf(-(z0 + bo)));
        out[4 * g + 1] = 1.0f / (1.0f + expf(-(z1 + bo)));
        out[4 * g + 2] = 1.0f / (1.0f + expf(-(z2 + bo)));
        out[4 * g + 3] = 1.0f / (1.0f + expf(-(z3 + bo)));
    }
}

extern "C" void kernel_launch(void* const* d_in, const int* in_sizes, int n_in,
                              void* d_out, int out_size) {
    const int*   dense_ids    = (const int*)  d_in[0];
    const int*   seq_ids      = (const int*)  d_in[1];
    const float* tables_dense = (const float*)d_in[2];
    const float* table_seq    = (const float*)d_in[3];
    const float* inner_w      = (const float*)d_in[4];
    const float* W1           = (const float*)d_in[5];
    const float* b1           = (const float*)d_in[6];
    const float* W2           = (const float*)d_in[7];
    const float* b2           = (const float*)d_in[8];
    float* out = (float*)d_out;
    (void)in_sizes; (void)n_in; (void)out_size;

    prep_kernel<<<(HID * 18 * 32 + 255) / 256, 256>>>(W1);
    gather_kernel<<<BB / 8, 256>>>(dense_ids, seq_ids, tables_dense, table_seq, inner_w);
    mlp_kernel<<<BB / 32, 256>>>(b1, W2, b2, out);
}

// round 6
// speedup vs baseline: 1.8668x; 1.8668x over previous
#include <cuda_runtime.h>
#include <math.h>

typedef unsigned long long ull;

#define BB   8192
#define VV   100000
#define ND   15
#define SL   50
#define HID  30
#define XROW 1024                 /* feature floats per row in global scratch */
#define X_STRIDE 1156             /* 4624 B ≡ 16 mod 128 -> conflict-free */
#define W1T_STRIDE 1152
#define RB   16

__device__ float g_X[(size_t)BB * XROW];     // 33.5 MB feature scratch
__device__ float g_W1T[32 * W1T_STRIDE];     // W1 transposed, rows 30,31 + tail zeroed
__device__ float g_head[64];                 // [0:32)=b1 padded, [32:64)=W2 padded

// ---------------- f32x2 helpers ----------------
__device__ __forceinline__ ull f2_pack(float x, float y) {
    ull r; asm("mov.b64 %0, {%1, %2};" : "=l"(r) : "f"(x), "f"(y)); return r;
}
__device__ __forceinline__ ull f2_mul(ull a, ull b) {
    ull r; asm("mul.rn.f32x2 %0, %1, %2;" : "=l"(r) : "l"(a), "l"(b)); return r;
}
__device__ __forceinline__ ull f2_add(ull a, ull b) {
    ull r; asm("add.rn.f32x2 %0, %1, %2;" : "=l"(r) : "l"(a), "l"(b)); return r;
}
__device__ __forceinline__ void f2_fma(ull& d, ull a, ull b) {
    asm("fma.rn.f32x2 %0, %1, %2, %0;" : "+l"(d) : "l"(a), "l"(b));
}
__device__ __forceinline__ float f2_hadd(ull a) {
    float lo, hi; asm("mov.b64 {%0, %1}, %2;" : "=f"(lo), "=f"(hi) : "l"(a));
    return lo + hi;
}

// ---------------- K1: gather (warp-per-row) + fused prep ----------------
__global__ __launch_bounds__(256) void gather_kernel(
    const int*   __restrict__ dense_ids,
    const int*   __restrict__ seq_ids,
    const float* __restrict__ tables_dense,
    const float* __restrict__ table_seq,
    const float* __restrict__ W1,
    const float* __restrict__ b1,
    const float* __restrict__ W2)
{
    if (blockIdx.x >= BB / 8) {
        // ---- prep path: transpose W1 into padded 32x1152, fill head consts ----
        int base = (blockIdx.x - BB / 8) * 256 + threadIdx.x;
        for (int e = base; e < 32 * W1T_STRIDE; e += 9 * 256) {
            int j = e / W1T_STRIDE;
            int k = e - j * W1T_STRIDE;
            g_W1T[e] = (j < HID && k < 1144) ? W1[k * HID + j] : 0.0f;
        }
        if (base < 64) {
            float v;
            if (base < 32) v = (base < HID) ? b1[base] : 0.0f;
            else           { int j = base - 32; v = (j < HID) ? W2[j] : 0.0f; }
            g_head[base] = v;
        }
        return;
    }

    const int l   = threadIdx.x & 31;
    const int w   = threadIdx.x >> 5;
    const int row = blockIdx.x * 8 + w;

    ull e[16];
    const ull* td = (const ull*)tables_dense;    // f32x2 view: 32 per embedding
    const int* dr = dense_ids + row * ND;
    #pragma unroll
    for (int f = 0; f < ND; f++) {
        int id = __ldg(dr + f);
        e[f] = __ldg(td + ((size_t)f * VV + (size_t)id) * 32 + l);
    }

    const int* sr = seq_ids + row * SL;
    const ull* ts = (const ull*)table_seq;
    ull acc = 0;   // bits(0) == (0.f,0.f)
    #pragma unroll 10
    for (int s = 0; s < SL; s++) {
        int id = __ldg(sr + s);
        acc = f2_add(acc, __ldg(ts + (size_t)id * 32 + l));
    }
    e[15] = f2_mul(acc, f2_pack(1.0f / 50.0f, 1.0f / 50.0f));

    ull* Xr = (ull*)(g_X + (size_t)row * XROW);
    #pragma unroll
    for (int f = 0; f < 16; f++) Xr[f * 32 + l] = e[f];
}

// ---------------- K2: pairs (shared) + MLP (f32x2, 4 units/warp) ----------------
__global__ __launch_bounds__(256) void mlp_kernel(
    const float* __restrict__ inner_w,
    const float* __restrict__ b2,
    float*       __restrict__ out)
{
    extern __shared__ float smem[];
    float* Xs = smem;                      // RB * X_STRIDE
    float* zp = smem + RB * X_STRIDE;      // 8 * 16 partials

    const int tid = threadIdx.x;
    const int l   = tid & 31;
    const int w   = tid >> 5;
    const int row0 = blockIdx.x * RB;

    // ---- Phase A: load 16 rows of features from global scratch ----
    for (int rr = w; rr < RB; rr += 8) {
        const float4* src = (const float4*)(g_X + (size_t)(row0 + rr) * XROW);
        float4* dst = (float4*)(Xs + rr * X_STRIDE);
        #pragma unroll
        for (int i = 0; i < 8; i++) dst[l + 32 * i] = __ldg(&src[l + 32 * i]);
    }
    if (tid < 192) Xs[(tid / 12) * X_STRIDE + 1144 + (tid % 12)] = 0.0f;  // pad
    __syncthreads();

    // ---- Phase B: 120 pairwise weighted inner products (R3-proven) ----
    {
        const int r    = l & 15;
        const int slot = l >> 4;
        const int q    = w * 2 + slot;           // 0..15
        const float* Xr = Xs + r * X_STRIDE;
        #pragma unroll
        for (int t = 0; t < 8; t++) {
            int p = q + 16 * t;
            if (p >= 120) break;
            int a = 0, rem = p, cnt = 15;
            while (rem >= cnt) { rem -= cnt; cnt--; a++; }
            int bb = a + 1 + rem;
            const float4* xa = (const float4*)(Xr + a  * 64);
            const float4* xb = (const float4*)(Xr + bb * 64);
            const float4* ww = (const float4*)(inner_w + p * 64);
            float s0 = 0.f, s1 = 0.f;
            #pragma unroll
            for (int i = 0; i < 16; i++) {
                float4 u = xa[i];
                float4 v = xb[i];
                float4 z = __ldg(&ww[i]);
                s0 += u.x * v.x * z.x + u.y * v.y * z.y;
                s1 += u.z * v.z * z.z + u.w * v.w * z.w;
            }
            Xs[r * X_STRIDE + 1024 + p] = s0 + s1;
        }
    }
    __syncthreads();

    // ---- Phase C: layer-1 GEMV. warp w -> units 4w..4w+3; lane = (row, k-half)
    {
        const int r  = l & 15;
        const int kh = l >> 4;
        const ulonglong2* xp = (const ulonglong2*)(Xs + r * X_STRIDE + kh * 576);
        const ulonglong2* p0 = (const ulonglong2*)(g_W1T + (4*w + 0) * W1T_STRIDE + kh * 576);
        const ulonglong2* p1 = (const ulonglong2*)(g_W1T + (4*w + 1) * W1T_STRIDE + kh * 576);
        const ulonglong2* p2 = (const ulonglong2*)(g_W1T + (4*w + 2) * W1T_STRIDE + kh * 576);
        const ulonglong2* p3 = (const ulonglong2*)(g_W1T + (4*w + 3) * W1T_STRIDE + kh * 576);
        ull a0 = 0, a1 = 0, a2 = 0, a3 = 0;
        #pragma unroll 4
        for (int i = 0; i < 144; i++) {          // 576 floats per half
            ulonglong2 x = xp[i];
            ulonglong2 u;
            u = __ldg(p0 + i); f2_fma(a0, x.x, u.x); f2_fma(a0, x.y, u.y);
            u = __ldg(p1 + i); f2_fma(a1, x.x, u.x); f2_fma(a1, x.y, u.y);
            u = __ldg(p2 + i); f2_fma(a2, x.x, u.x); f2_fma(a2, x.y, u.y);
            u = __ldg(p3 + i); f2_fma(a3, x.x, u.x); f2_fma(a3, x.y, u.y);
        }
        float s0 = f2_hadd(a0), s1 = f2_hadd(a1), s2 = f2_hadd(a2), s3 = f2_hadd(a3);
        s0 += __shfl_xor_sync(0xffffffffu, s0, 16);
        s1 += __shfl_xor_sync(0xffffffffu, s1, 16);
        s2 += __shfl_xor_sync(0xffffffffu, s2, 16);
        s3 += __shfl_xor_sync(0xffffffffu, s3, 16);
        if (l < 16) {
            int j = 4 * w;
            const float* hb = g_head;        // b1 padded
            const float* hw = g_head + 32;   // W2 padded (zeros for j>=30)
            float z = fmaxf(s0 + hb[j    ], 0.f) * hw[j    ]
                    + fmaxf(s1 + hb[j + 1], 0.f) * hw[j + 1]
                    + fmaxf(s2 + hb[j + 2], 0.f) * hw[j + 2]
                    + fmaxf(s3 + hb[j + 3], 0.f) * hw[j + 3];
            zp[w * 16 + l] = z;
        }
    }
    __syncthreads();

    // ---- Phase D: head reduction + sigmoid (deterministic order) ----
    if (tid < RB) {
        float z = 0.f;
        #pragma unroll
        for (int k = 0; k < 8; k++) z += zp[k * 16 + tid];
        z += __ldg(b2);
        out[row0 + tid] = 1.0f / (1.0f + expf(-z));
    }
}

extern "C" void kernel_launch(void* const* d_in, const int* in_sizes, int n_in,
                              void* d_out, int out_size) {
    const int*   dense_ids    = (const int*)  d_in[0];
    const int*   seq_ids      = (const int*)  d_in[1];
    const float* tables_dense = (const float*)d_in[2];
    const float* table_seq    = (const float*)d_in[3];
    const float* inner_w      = (const float*)d_in[4];
    const float* W1           = (const float*)d_in[5];
    const float* b1           = (const float*)d_in[6];
    const float* W2           = (const float*)d_in[7];
    const float* b2           = (const float*)d_in[8];
    float* out = (float*)d_out;
    (void)in_sizes; (void)n_in; (void)out_size;

    gather_kernel<<<BB / 8 + 9, 256>>>(dense_ids, seq_ids, tables_dense,
                                       table_seq, W1, b1, W2);

    const size_t smem = (size_t)(RB * X_STRIDE + 8 * 16) * sizeof(float);  // 74496 B
    cudaFuncSetAttribute(mlp_kernel, cudaFuncAttributeMaxDynamicSharedMemorySize, (int)smem);
    mlp_kernel<<<BB / RB, 256, smem>>>(inner_w, b2, out);
}

// round 7
// speedup vs baseline: 3.0716x; 1.6454x over previous
#include <cuda_runtime.h>
#include <math.h>

typedef unsigned long long ull;

#define BB   8192
#define VV   100000
#define ND   15
#define SL   50
#define HID  30

// X scratch: [row][0..1023 features | 1024..1143 lp | 1144..1151 zero] row-major
__device__ float g_X[(size_t)BB * 1152];
// W1 transposed to n-major: g_W1NK[n][k], n<32 (rows 30,31 zero), k<1152 (tail zero)
__device__ float g_W1NK[32 * 1152];

// ---------------- f32x2 helpers ----------------
__device__ __forceinline__ ull f2_pack(float x, float y) {
    ull r; asm("mov.b64 %0, {%1, %2};" : "=l"(r) : "f"(x), "f"(y)); return r;
}
__device__ __forceinline__ ull f2_mul(ull a, ull b) {
    ull r; asm("mul.rn.f32x2 %0, %1, %2;" : "=l"(r) : "l"(a), "l"(b)); return r;
}
__device__ __forceinline__ ull f2_add(ull a, ull b) {
    ull r; asm("add.rn.f32x2 %0, %1, %2;" : "=l"(r) : "l"(a), "l"(b)); return r;
}
__device__ __forceinline__ void f2_fma(ull& d, ull a, ull b) {
    asm("fma.rn.f32x2 %0, %1, %2, %0;" : "+l"(d) : "l"(a), "l"(b));
}
__device__ __forceinline__ float f2_hadd(ull a) {
    float lo, hi; asm("mov.b64 {%0, %1}, %2;" : "=f"(lo), "=f"(hi) : "l"(a));
    return lo + hi;
}

// ---------------- K1: gather + fused pairwise (warp-autonomous) + W prep ----------------
__global__ __launch_bounds__(256) void gather_kernel(
    const int*   __restrict__ dense_ids,
    const int*   __restrict__ seq_ids,
    const float* __restrict__ tables_dense,
    const float* __restrict__ table_seq,
    const float* __restrict__ inner_w,
    const float* __restrict__ W1)
{
    if (blockIdx.x >= BB / 8) {
        // prep path: W1 [1144x30] -> g_W1NK [32x1152] n-major, zero-padded
        int base = (blockIdx.x - BB / 8) * 256 + threadIdx.x;   // 0..2303
        for (int e = base; e < 32 * 1152; e += 9 * 256) {
            int n = e / 1152;
            int k = e - n * 1152;
            g_W1NK[e] = (n < HID && k < 1144) ? W1[k * HID + n] : 0.0f;
        }
        return;
    }

    __shared__ float Xs[8 * 1028];        // per-warp 1028-float slice (bank-shifted)

    const int l   = threadIdx.x & 31;
    const int w   = threadIdx.x >> 5;
    const int row = blockIdx.x * 8 + w;

    // ---- gather dense features (random, DRAM) ----
    ull e[16];
    const ull* td = (const ull*)tables_dense;     // f32x2 view: 32 per embedding
    const int* dr = dense_ids + row * ND;
    #pragma unroll
    for (int f = 0; f < ND; f++) {
        int id = __ldg(dr + f);
        e[f] = __ldg(td + ((size_t)f * VV + (size_t)id) * 32 + l);
    }

    // ---- sequence mean (feature 15, L2-resident table) ----
    const int* sr = seq_ids + row * SL;
    const ull* ts = (const ull*)table_seq;
    ull acc = 0;                                   // bits(0) == (0.f, 0.f)
    #pragma unroll 10
    for (int s = 0; s < SL; s++) {
        int id = __ldg(sr + s);
        acc = f2_add(acc, __ldg(ts + (size_t)id * 32 + l));
    }
    e[15] = f2_mul(acc, f2_pack(1.0f / 50.0f, 1.0f / 50.0f));

    // ---- store features: own smem slice (for pairwise) + global X row ----
    ull* Xw = (ull*)(Xs + w * 1028);
    ull* Xg = (ull*)(g_X + (size_t)row * 1152);
    #pragma unroll
    for (int f = 0; f < 16; f++) {
        Xw[f * 32 + l] = e[f];
        Xg[f * 32 + l] = e[f];
    }
    if (l < 8) g_X[(size_t)row * 1152 + 1144 + l] = 0.0f;    // zero pad
    __syncwarp();

    // ---- pairwise: warp w handles its own row; lane s -> pairs s, s+32, s+64, s+96 ----
    const float* Xr = Xs + w * 1028;
    const int s = l;
    #pragma unroll
    for (int t = 0; t < 4; t++) {
        int p = s + 32 * t;
        if (p >= 120) break;
        int a = 0, rem = p, cnt = 15;
        while (rem >= cnt) { rem -= cnt; cnt--; a++; }
        int b = a + 1 + rem;
        const float* pa = Xr + a * 64;
        const float* pb = Xr + b * 64;
        const float* pw = inner_w + p * 64;
        ull d = 0;
        #pragma unroll
        for (int ii = 0; ii < 16; ii++) {
            int i = (s + ii) & 15;                 // lane rotation: 4-phase-optimal LDS
            ulonglong2 xa = *(const ulonglong2*)(pa + i * 4);
            ulonglong2 xb = *(const ulonglong2*)(pb + i * 4);
            ulonglong2 wv = __ldg((const ulonglong2*)(pw + i * 4));
            f2_fma(d, f2_mul(xa.x, xb.x), wv.x);
            f2_fma(d, f2_mul(xa.y, xb.y), wv.y);
        }
        g_X[(size_t)row * 1152 + 1024 + p] = f2_hadd(d);
    }
}

// ---------------- K2: tiled GEMM (32 rows x 32 units, KC=64) + fused head ----------------
__global__ __launch_bounds__(128) void mlp_kernel(
    const float* __restrict__ b1,
    const float* __restrict__ W2,
    const float* __restrict__ b2,
    float*       __restrict__ out)
{
    __shared__ float Xsh[32 * 68];     // [m][k] stride 68 (272 B ≡ 16 mod 128)
    __shared__ float Wsh[32 * 68];     // [n][k] stride 68

    const int t    = threadIdx.x;
    const int row0 = blockIdx.x * 32;
    const int cp   = t & 15;           // col: cp and cp+16
    const int rq   = t >> 4;           // row quad: rows rq*4 .. rq*4+3

    ull acc[4][2];
    #pragma unroll
    for (int i = 0; i < 4; i++) { acc[i][0] = 0; acc[i][1] = 0; }

    for (int c = 0; c < 18; c++) {
        const int koff = c * 64;
        // stage X tile: 32 rows x 64 k (direct copy, coalesced)
        #pragma unroll
        for (int q = 0; q < 2; q++) {
            #pragma unroll
            for (int p = 0; p < 2; p++) {
                int m  = (t >> 3) + 16 * q;
                int kk = (t & 7) * 4 + 32 * p;
                float4 v = __ldg((const float4*)(g_X + (size_t)(row0 + m) * 1152 + koff + kk));
                *(float4*)(Xsh + m * 68 + kk) = v;
            }
        }
        // stage W tile: 32 units x 64 k (direct copy)
        #pragma unroll
        for (int p = 0; p < 4; p++) {
            int n  = t >> 2;
            int kk = (t & 3) * 4 + 16 * p;
            float4 v = __ldg((const float4*)(g_W1NK + n * 1152 + koff + kk));
            *(float4*)(Wsh + n * 68 + kk) = v;
        }
        __syncthreads();

        #pragma unroll
        for (int k4 = 0; k4 < 16; k4++) {
            ulonglong2 w0 = *(const ulonglong2*)(Wsh + cp * 68 + k4 * 4);
            ulonglong2 w1 = *(const ulonglong2*)(Wsh + (cp + 16) * 68 + k4 * 4);
            #pragma unroll
            for (int i = 0; i < 4; i++) {
                ulonglong2 x = *(const ulonglong2*)(Xsh + (rq * 4 + i) * 68 + k4 * 4);
                f2_fma(acc[i][0], x.x, w0.x);
                f2_fma(acc[i][0], x.y, w0.y);
                f2_fma(acc[i][1], x.x, w1.x);
                f2_fma(acc[i][1], x.y, w1.y);
            }
        }
        __syncthreads();
    }

    // ---- head: relu, W2 scale, reduce over 32 cols, sigmoid ----
    const int n1 = cp + 16;
    float bb0 = __ldg(b1 + cp);
    float w20 = __ldg(W2 + cp);
    float bb1 = (n1 < HID) ? __ldg(b1 + n1) : 0.0f;
    float w21 = (n1 < HID) ? __ldg(W2 + n1) : 0.0f;

    float z[4];
    #pragma unroll
    for (int i = 0; i < 4; i++) {
        float s0 = f2_hadd(acc[i][0]);
        float s1 = f2_hadd(acc[i][1]);
        z[i] = fmaxf(s0 + bb0, 0.0f) * w20 + fmaxf(s1 + bb1, 0.0f) * w21;
    }
    #pragma unroll
    for (int o = 1; o < 16; o <<= 1) {
        #pragma unroll
        for (int i = 0; i < 4; i++)
            z[i] += __shfl_xor_sync(0xffffffffu, z[i], o);
    }
    if (cp == 0) {
        float bo = __ldg(b2);
        #pragma unroll
        for (int i = 0; i < 4; i++)
            out[row0 + rq * 4 + i] = 1.0f / (1.0f + expf(-(z[i] + bo)));
    }
}

extern "C" void kernel_launch(void* const* d_in, const int* in_sizes, int n_in,
                              void* d_out, int out_size) {
    const int*   dense_ids    = (const int*)  d_in[0];
    const int*   seq_ids      = (const int*)  d_in[1];
    const float* tables_dense = (const float*)d_in[2];
    const float* table_seq    = (const float*)d_in[3];
    const float* inner_w      = (const float*)d_in[4];
    const float* W1           = (const float*)d_in[5];
    const float* b1           = (const float*)d_in[6];
    const float* W2           = (const float*)d_in[7];
    const float* b2           = (const float*)d_in[8];
    float* out = (float*)d_out;
    (void)in_sizes; (void)n_in; (void)out_size;

    gather_kernel<<<BB / 8 + 9, 256>>>(dense_ids, seq_ids, tables_dense,
                                       table_seq, inner_w, W1);
    mlp_kernel<<<BB / 32, 128>>>(b1, W2, b2, out);
}